// round 3
// baseline (speedup 1.0000x reference)
#include <cuda_runtime.h>

// 4 rows (64B in / 64B out) per thread: front-batched LDG.128 x4 raises
// per-warp MLP so the HBM pipe stays saturated.
__global__ void quantum_probs_kernel4(const float4* __restrict__ in,
                                      float4* __restrict__ out,
                                      int n) {
    int base = (blockIdx.x * blockDim.x + threadIdx.x) * 4;
    if (base + 3 < n) {
        // Batched independent loads (MLP_p1 = 4)
        float4 r0 = in[base + 0];
        float4 r1 = in[base + 1];
        float4 r2 = in[base + 2];
        float4 r3 = in[base + 3];

        float s, c;
        __sincosf(r0.x * 0.5f, &s, &c);
        float c20 = c * c, s20 = s * s;
        __sincosf(r1.x * 0.5f, &s, &c);
        float c21 = c * c, s21 = s * s;
        __sincosf(r2.x * 0.5f, &s, &c);
        float c22 = c * c, s22 = s * s;
        __sincosf(r3.x * 0.5f, &s, &c);
        float c23 = c * c, s23 = s * s;

        out[base + 0] = make_float4(c20 * c20, c20 * s20, s20 * s20, s20 * c20);
        out[base + 1] = make_float4(c21 * c21, c21 * s21, s21 * s21, s21 * c21);
        out[base + 2] = make_float4(c22 * c22, c22 * s22, s22 * s22, s22 * c22);
        out[base + 3] = make_float4(c23 * c23, c23 * s23, s23 * s23, s23 * c23);
    } else {
        // Tail (never taken for N=16M, but keep it correct for any N)
        for (int i = base; i < n; ++i) {
            float4 r = in[i];
            float s, c;
            __sincosf(r.x * 0.5f, &s, &c);
            float c2 = c * c, s2 = s * s;
            out[i] = make_float4(c2 * c2, c2 * s2, s2 * s2, s2 * c2);
        }
    }
}

extern "C" void kernel_launch(void* const* d_in, const int* in_sizes, int n_in,
                              void* d_out, int out_size) {
    const float4* in = (const float4*)d_in[0];
    float4* out = (float4*)d_out;
    int n = in_sizes[0] / 4;                  // N rows
    int threads = 256;
    int rows_per_block = threads * 4;
    int blocks = (n + rows_per_block - 1) / rows_per_block;
    quantum_probs_kernel4<<<blocks, threads>>>(in, out, n);
}

// round 5
// speedup vs baseline: 1.0538x; 1.0538x over previous
#include <cuda_runtime.h>

// Block-strided 4x batching: each thread handles rows
//   base + tid + k*blockDim  (k = 0..3)
// -> every LDG.128/STG.128 is perfectly coalesced across the warp
//    (contiguous 512B per warp per instruction), AND the 4 loads are
//    independent (front-batched, MLP_p1 = 4).
__global__ void quantum_probs_kernel_bs4(const float4* __restrict__ in,
                                         float4* __restrict__ out,
                                         int n) {
    const int tid = threadIdx.x;
    const int base = blockIdx.x * (blockDim.x * 4) + tid;
    const int stride = blockDim.x;

    int i0 = base;
    int i1 = base + stride;
    int i2 = base + 2 * stride;
    int i3 = base + 3 * stride;

    if (i3 < n) {
        float4 r0 = in[i0];
        float4 r1 = in[i1];
        float4 r2 = in[i2];
        float4 r3 = in[i3];

        float s, c;
        __sincosf(r0.x * 0.5f, &s, &c);
        float c20 = c * c, s20 = s * s;
        __sincosf(r1.x * 0.5f, &s, &c);
        float c21 = c * c, s21 = s * s;
        __sincosf(r2.x * 0.5f, &s, &c);
        float c22 = c * c, s22 = s * s;
        __sincosf(r3.x * 0.5f, &s, &c);
        float c23 = c * c, s23 = s * s;

        out[i0] = make_float4(c20 * c20, c20 * s20, s20 * s20, s20 * c20);
        out[i1] = make_float4(c21 * c21, c21 * s21, s21 * s21, s21 * c21);
        out[i2] = make_float4(c22 * c22, c22 * s22, s22 * s22, s22 * c22);
        out[i3] = make_float4(c23 * c23, c23 * s23, s23 * s23, s23 * c23);
    } else {
        // Tail path (not taken for N = 16M with 1024 rows/block)
        for (int i = i0; i < n; i += stride) {
            float4 r = in[i];
            float s, c;
            __sincosf(r.x * 0.5f, &s, &c);
            float c2 = c * c, s2 = s * s;
            out[i] = make_float4(c2 * c2, c2 * s2, s2 * s2, s2 * c2);
        }
    }
}

extern "C" void kernel_launch(void* const* d_in, const int* in_sizes, int n_in,
                              void* d_out, int out_size) {
    const float4* in = (const float4*)d_in[0];
    float4* out = (float4*)d_out;
    int n = in_sizes[0] / 4;                  // N rows
    int threads = 256;
    int rows_per_block = threads * 4;
    int blocks = (n + rows_per_block - 1) / rows_per_block;
    quantum_probs_kernel_bs4<<<blocks, threads>>>(in, out, n);
}

// round 6
// speedup vs baseline: 1.0546x; 1.0008x over previous
#include <cuda_runtime.h>

// 8x block-strided batching + streaming cache hints.
//  - Each LDG/STG.128 is warp-coalesced (contiguous 512B per instruction).
//  - 8 independent front-batched loads per thread (MLP_p1 = 8).
//  - __ldcs/__stcs: evict-first policy; zero reuse, so don't let dead
//    lines occupy L2 and delay the fill/writeback pipeline.
__global__ void __launch_bounds__(256)
quantum_probs_kernel_bs8(const float4* __restrict__ in,
                         float4* __restrict__ out,
                         int n) {
    const int tid = threadIdx.x;
    const int stride = blockDim.x;
    const int base = blockIdx.x * (stride * 8) + tid;

    if (base + 7 * stride < n) {
        float4 r[8];
#pragma unroll
        for (int k = 0; k < 8; ++k)
            r[k] = __ldcs(&in[base + k * stride]);

        float4 o[8];
#pragma unroll
        for (int k = 0; k < 8; ++k) {
            float s, c;
            __sincosf(r[k].x * 0.5f, &s, &c);
            float c2 = c * c, s2 = s * s;
            o[k] = make_float4(c2 * c2, c2 * s2, s2 * s2, s2 * c2);
        }

#pragma unroll
        for (int k = 0; k < 8; ++k)
            __stcs(&out[base + k * stride], o[k]);
    } else {
        // Tail path (not taken for N = 16M: 2048 rows/block divides N)
        for (int i = base; i < n; i += stride) {
            float4 rr = __ldcs(&in[i]);
            float s, c;
            __sincosf(rr.x * 0.5f, &s, &c);
            float c2 = c * c, s2 = s * s;
            __stcs(&out[i], make_float4(c2 * c2, c2 * s2, s2 * s2, s2 * c2));
        }
    }
}

extern "C" void kernel_launch(void* const* d_in, const int* in_sizes, int n_in,
                              void* d_out, int out_size) {
    const float4* in = (const float4*)d_in[0];
    float4* out = (float4*)d_out;
    int n = in_sizes[0] / 4;                  // N rows
    int threads = 256;
    int rows_per_block = threads * 8;
    int blocks = (n + rows_per_block - 1) / rows_per_block;
    quantum_probs_kernel_bs8<<<blocks, threads>>>(in, out, n);
}

// round 7
// speedup vs baseline: 1.0571x; 1.0023x over previous
#include <cuda_runtime.h>

// Best-measured geometry (R3: 4x block-strided, 256 thr, grid 16384)
// plus streaming cache hints, now unconfounded from the MLP=8 change.
//  - Each LDG/STG.128 warp-coalesced (contiguous 512B per instruction).
//  - 4 independent front-batched loads per thread (MLP_p1 = 4: empirical
//    optimum — MLP=8 raised cross-CTA L1tex-queue spread with no latency win).
//  - __ldcs/__stcs: evict-first; zero-reuse stream shouldn't occupy L2.
__global__ void __launch_bounds__(256)
quantum_probs_kernel_bs4s(const float4* __restrict__ in,
                          float4* __restrict__ out,
                          int n) {
    const int tid = threadIdx.x;
    const int stride = blockDim.x;
    const int base = blockIdx.x * (stride * 4) + tid;

    if (base + 3 * stride < n) {
        float4 r0 = __ldcs(&in[base + 0 * stride]);
        float4 r1 = __ldcs(&in[base + 1 * stride]);
        float4 r2 = __ldcs(&in[base + 2 * stride]);
        float4 r3 = __ldcs(&in[base + 3 * stride]);

        float s, c;
        __sincosf(r0.x * 0.5f, &s, &c);
        float c20 = c * c, s20 = s * s;
        __sincosf(r1.x * 0.5f, &s, &c);
        float c21 = c * c, s21 = s * s;
        __sincosf(r2.x * 0.5f, &s, &c);
        float c22 = c * c, s22 = s * s;
        __sincosf(r3.x * 0.5f, &s, &c);
        float c23 = c * c, s23 = s * s;

        __stcs(&out[base + 0 * stride], make_float4(c20 * c20, c20 * s20, s20 * s20, s20 * c20));
        __stcs(&out[base + 1 * stride], make_float4(c21 * c21, c21 * s21, s21 * s21, s21 * c21));
        __stcs(&out[base + 2 * stride], make_float4(c22 * c22, c22 * s22, s22 * s22, s22 * c22));
        __stcs(&out[base + 3 * stride], make_float4(c23 * c23, c23 * s23, s23 * s23, s23 * c23));
    } else {
        // Tail path (not taken for N = 16M: 1024 rows/block divides N)
        for (int i = base; i < n; i += stride) {
            float4 rr = __ldcs(&in[i]);
            float s, c;
            __sincosf(rr.x * 0.5f, &s, &c);
            float c2 = c * c, s2 = s * s;
            __stcs(&out[i], make_float4(c2 * c2, c2 * s2, s2 * s2, s2 * c2));
        }
    }
}

extern "C" void kernel_launch(void* const* d_in, const int* in_sizes, int n_in,
                              void* d_out, int out_size) {
    const float4* in = (const float4*)d_in[0];
    float4* out = (float4*)d_out;
    int n = in_sizes[0] / 4;                  // N rows
    int threads = 256;
    int rows_per_block = threads * 4;
    int blocks = (n + rows_per_block - 1) / rows_per_block;
    quantum_probs_kernel_bs4s<<<blocks, threads>>>(in, out, n);
}